// round 11
// baseline (speedup 1.0000x reference)
#include <cuda_runtime.h>
#include <cuda_bf16.h>
#include <math.h>
#include <stdint.h>

#define N_E   2048
#define HEAD  8
#define HLR   4096

// ---------------- small fp32 scratch ----------------
__device__ float g_sumsq[3 * N_E];
__device__ float g_inv[3 * N_E];            // rsqrt norms (q,k,d)
__device__ float g_rowsum[HEAD * N_E];      // softmax denominators

// ---------------- bf16 split operands ----------------
__device__ __nv_bfloat16 bx_hi[(size_t)16384 * 512];        // xr[n*8+r][f]
__device__ __nv_bfloat16 bx_lo[(size_t)16384 * 512];
__device__ __nv_bfloat16 bw_hi[(size_t)1536 * 512];         // W concat [hq'][f]
__device__ __nv_bfloat16 bw_lo[(size_t)1536 * 512];
__device__ __nv_bfloat16 bq_hi[(size_t)HEAD * N_E * 512];   // unnormalized q [h][n][lr]
__device__ __nv_bfloat16 bq_lo[(size_t)HEAD * N_E * 512];
__device__ __nv_bfloat16 bk_hi[(size_t)HEAD * N_E * 512];
__device__ __nv_bfloat16 bk_lo[(size_t)HEAD * N_E * 512];
__device__ __nv_bfloat16 bd_hi[(size_t)HEAD * N_E * 512];   // unnormalized d [h][m][lr]
__device__ __nv_bfloat16 bd_lo[(size_t)HEAD * N_E * 512];
__device__ __nv_bfloat16 bs_hi[(size_t)HEAD * N_E * N_E];   // exp-weights [h][n][m]
__device__ __nv_bfloat16 bs_lo[(size_t)HEAD * N_E * N_E];
__device__ __nv_bfloat16 bdt_hi[(size_t)HEAD * 512 * N_E];  // dT [h][lr][m], inv_d folded
__device__ __nv_bfloat16 bdt_lo[(size_t)HEAD * 512 * N_E];

// ---------------- warp-MMA GEMM core: 128x256x64, 8 warps (2x4), warp tile 64x64 ----------------
#define BM 128
#define BN 256
#define BK 64
#define STG 3
#define STAGE_BYTES ((BM + BN) * 128)          // 49152
#define SMEM_DYN (STG * STAGE_BYTES)           // 147456

__device__ __forceinline__ void cp16(uint32_t s, const void* g) {
    asm volatile("cp.async.cg.shared.global [%0], [%1], 16;\n"
                 :: "r"(s), "l"(__cvta_generic_to_global(g)));
}
__device__ __forceinline__ void cp_commit() { asm volatile("cp.async.commit_group;\n" ::: "memory"); }
__device__ __forceinline__ void cp_wait1()  { asm volatile("cp.async.wait_group 1;\n" ::: "memory"); }

__device__ __forceinline__ void ldsm4(uint32_t* r, uint32_t a) {
    asm volatile("ldmatrix.sync.aligned.m8n8.x4.shared.b16 {%0,%1,%2,%3}, [%4];"
                 : "=r"(r[0]), "=r"(r[1]), "=r"(r[2]), "=r"(r[3]) : "r"(a));
}
__device__ __forceinline__ void mma16816(float* c, const uint32_t* a, const uint32_t* b) {
    asm volatile("mma.sync.aligned.m16n8k16.row.col.f32.bf16.bf16.f32 "
                 "{%0,%1,%2,%3}, {%4,%5,%6,%7}, {%8,%9}, {%0,%1,%2,%3};"
                 : "+f"(c[0]), "+f"(c[1]), "+f"(c[2]), "+f"(c[3])
                 : "r"(a[0]), "r"(a[1]), "r"(a[2]), "r"(a[3]), "r"(b[0]), "r"(b[1]));
}

// one stage: A 128x64 bf16 (16KB), B 256x64 bf16 (32KB), 128B rows, unit-XOR swizzle
__device__ __forceinline__ void load_stage(uint32_t s,
                                           const __nv_bfloat16* __restrict__ A,
                                           const __nv_bfloat16* __restrict__ B, int ldk) {
    const int tid = threadIdx.x;
#pragma unroll
    for (int i = 0; i < 4; i++) {
        int idx = tid + i * 256, r = idx >> 3, c = idx & 7;
        cp16(s + r * 128 + ((c ^ (r & 7)) << 4), A + (size_t)r * ldk + c * 8);
    }
#pragma unroll
    for (int i = 0; i < 8; i++) {
        int idx = tid + i * 256, r = idx >> 3, c = idx & 7;
        cp16(s + BM * 128 + r * 128 + ((c ^ (r & 7)) << 4), B + (size_t)r * ldk + c * 8);
    }
    cp_commit();
}

// 3-pass hi/lo mainloop with fragment double-buffering across ks
__device__ __forceinline__ void gemm_run(float (&acc)[4][8][4],
    const __nv_bfloat16* __restrict__ Ahi, const __nv_bfloat16* __restrict__ Alo,
    const __nv_bfloat16* __restrict__ Bhi, const __nv_bfloat16* __restrict__ Blo,
    const int ldk, const int KT)
{
    extern __shared__ char smem[];
    const uint32_t sb = (uint32_t)__cvta_generic_to_shared(smem);
    const int tid = threadIdx.x, lid = tid & 31, wid = tid >> 5;
    const int mw = wid >> 2, nw = wid & 3;
    const int TT = 3 * KT;

    const __nv_bfloat16* Ap[3] = {Ahi, Alo, Ahi};
    const __nv_bfloat16* Bp[3] = {Bhi, Bhi, Blo};

#pragma unroll
    for (int mf = 0; mf < 4; mf++)
#pragma unroll
        for (int j = 0; j < 8; j++)
#pragma unroll
            for (int e = 0; e < 4; e++) acc[mf][j][e] = 0.f;

    int rowA[4], rowB[4];
#pragma unroll
    for (int mf = 0; mf < 4; mf++)
        rowA[mf] = mw * 64 + mf * 16 + ((lid >> 3) & 1) * 8 + (lid & 7);
#pragma unroll
    for (int nf = 0; nf < 4; nf++)
        rowB[nf] = nw * 64 + nf * 16 + (lid >> 4) * 8 + (lid & 7);
    const int uhA = lid >> 4;
    const int uB  = (lid >> 3) & 1;

#pragma unroll
    for (int s = 0; s < STG - 1; s++)
        load_stage(sb + s * STAGE_BYTES, Ap[0] + (size_t)s * BK, Bp[0] + (size_t)s * BK, ldk);

    uint32_t a[2][4][4], b[2][4][4];

    for (int t = 0; t < TT; t++) {
        cp_wait1();
        __syncthreads();
        const uint32_t sA = sb + (t % STG) * STAGE_BYTES;
        const uint32_t sB = sA + BM * 128;

        // ks=0 fragments into buffer 0 (starts smem reads immediately after barrier)
#pragma unroll
        for (int mf = 0; mf < 4; mf++)
            ldsm4(a[0][mf], sA + rowA[mf] * 128 + ((uhA ^ (rowA[mf] & 7)) << 4));
#pragma unroll
        for (int nf = 0; nf < 4; nf++)
            ldsm4(b[0][nf], sB + rowB[nf] * 128 + ((uB ^ (rowB[nf] & 7)) << 4));

        // issue next-stage cp.asyncs; their issue cycles cover the LDSM latency above
        int tn = t + STG - 1;
        if (tn < TT) {
            int p = tn / KT, kt = tn - p * KT;
            load_stage(sb + (tn % STG) * STAGE_BYTES,
                       Ap[p] + (size_t)kt * BK, Bp[p] + (size_t)kt * BK, ldk);
        } else {
            cp_commit();
        }

#pragma unroll
        for (int ks = 0; ks < 4; ks++) {
            const int cur = ks & 1, nxt = cur ^ 1;
            if (ks < 3) {   // prefetch ks+1 fragments while MMAs for ks execute
#pragma unroll
                for (int mf = 0; mf < 4; mf++)
                    ldsm4(a[nxt][mf], sA + rowA[mf] * 128 + ((((ks + 1) * 2 + uhA) ^ (rowA[mf] & 7)) << 4));
#pragma unroll
                for (int nf = 0; nf < 4; nf++)
                    ldsm4(b[nxt][nf], sB + rowB[nf] * 128 + ((((ks + 1) * 2 + uB) ^ (rowB[nf] & 7)) << 4));
            }
#pragma unroll
            for (int mf = 0; mf < 4; mf++)
#pragma unroll
                for (int nf = 0; nf < 4; nf++) {
                    mma16816(acc[mf][nf * 2],     a[cur][mf], &b[cur][nf][0]);
                    mma16816(acc[mf][nf * 2 + 1], a[cur][mf], &b[cur][nf][2]);
                }
        }
    }
}

__device__ __forceinline__ void split_bf16(float v, __nv_bfloat16& hi, __nv_bfloat16& lo) {
    hi = __float2bfloat16(v);
    lo = __float2bfloat16(v - __bfloat162float(hi));
}

// ============================================================
// GEMM 1: proj  C[hq'(1536)][c(16384)] = Wcat . xr^T
// epilogue: bf16-split scatter to bq/bk/bd + per-n sumsq atomics
// ============================================================
__global__ __launch_bounds__(256) void proj_gemm() {
    const int row0 = blockIdx.y * BM, col0 = blockIdx.x * BN;
    float acc[4][8][4];
    gemm_run(acc, bw_hi + (size_t)row0 * 512, bw_lo + (size_t)row0 * 512,
                  bx_hi + (size_t)col0 * 512, bx_lo + (size_t)col0 * 512, 512, 8);
    const int lid = threadIdx.x & 31, wid = threadIdx.x >> 5;
    const int mw = wid >> 2, nw = wid & 3;
    const int which = row0 >> 9;                         // 0=q,1=k,2=d
    __nv_bfloat16* DH = (which == 0) ? bq_hi : (which == 1) ? bk_hi : bd_hi;
    __nv_bfloat16* DL = (which == 0) ? bq_lo : (which == 1) ? bk_lo : bd_lo;

    float psum[8];
#pragma unroll
    for (int j = 0; j < 8; j++) psum[j] = 0.f;

#pragma unroll
    for (int mf = 0; mf < 4; mf++) {
        int row = row0 + mw * 64 + mf * 16 + (lid >> 2);
        int hq = row & 511, h = hq >> 6, ql = hq & 63;
#pragma unroll
        for (int j = 0; j < 8; j++) {
            int col = col0 + nw * 64 + j * 8 + ((lid & 3) << 1);
            int n = col >> 3, r = col & 7;
            float v0 = acc[mf][j][0], v1 = acc[mf][j][1];
            float v2 = acc[mf][j][2], v3 = acc[mf][j][3];
            psum[j] += v0 * v0 + v1 * v1 + v2 * v2 + v3 * v3;
            size_t o0 = ((size_t)(h * N_E + n)) * 512 + ql * 8 + r;
            __nv_bfloat16 h0, h1, h2, h3, l0, l1, l2, l3;
            split_bf16(v0, h0, l0); split_bf16(v1, h1, l1);
            split_bf16(v2, h2, l2); split_bf16(v3, h3, l3);
            *(__nv_bfloat162*)&DH[o0]      = __halves2bfloat162(h0, h1);
            *(__nv_bfloat162*)&DL[o0]      = __halves2bfloat162(l0, l1);
            *(__nv_bfloat162*)&DH[o0 + 64] = __halves2bfloat162(h2, h3);   // row ql+8
            *(__nv_bfloat162*)&DL[o0 + 64] = __halves2bfloat162(l2, l3);
        }
    }
#pragma unroll
    for (int j = 0; j < 8; j++) {
#pragma unroll
        for (int o = 16; o; o >>= 1) psum[j] += __shfl_xor_sync(0xffffffffu, psum[j], o);
    }
    if (lid == 0) {
        int nb = (col0 >> 3) + nw * 8;
#pragma unroll
        for (int j = 0; j < 8; j++)
            atomicAdd(&g_sumsq[which * N_E + nb + j], psum[j]);
    }
}

// ============================================================
// GEMM 2: scores -> exp-weights.  logit = (q.k)*inv_q[n]*inv_k[m], |logit|<=1
// ============================================================
__global__ __launch_bounds__(256) void scores_gemm() {
    const int h = blockIdx.z, row0 = blockIdx.y * BM, col0 = blockIdx.x * BN;
    const size_t ho = (size_t)h * N_E * 512;
    float acc[4][8][4];
    gemm_run(acc, bq_hi + ho + (size_t)row0 * 512, bq_lo + ho + (size_t)row0 * 512,
                  bk_hi + ho + (size_t)col0 * 512, bk_lo + ho + (size_t)col0 * 512, 512, 8);
    const int lid = threadIdx.x & 31, wid = threadIdx.x >> 5;
    const int mw = wid >> 2, nw = wid & 3;
    __nv_bfloat16* SH = bs_hi + (size_t)h * N_E * N_E;
    __nv_bfloat16* SL = bs_lo + (size_t)h * N_E * N_E;

    float prow[4][2];
#pragma unroll
    for (int mf = 0; mf < 4; mf++) { prow[mf][0] = 0.f; prow[mf][1] = 0.f; }

#pragma unroll
    for (int mf = 0; mf < 4; mf++) {
        int rA = row0 + mw * 64 + mf * 16 + (lid >> 2);
        float iq0 = g_inv[rA], iq1 = g_inv[rA + 8];
#pragma unroll
        for (int j = 0; j < 8; j++) {
            int col = col0 + nw * 64 + j * 8 + ((lid & 3) << 1);
            float ik0 = g_inv[N_E + col], ik1 = g_inv[N_E + col + 1];
            float e0 = __expf(acc[mf][j][0] * iq0 * ik0);
            float e1 = __expf(acc[mf][j][1] * iq0 * ik1);
            float e2 = __expf(acc[mf][j][2] * iq1 * ik0);
            float e3 = __expf(acc[mf][j][3] * iq1 * ik1);
            prow[mf][0] += e0 + e1;
            prow[mf][1] += e2 + e3;
            __nv_bfloat16 h0, h1, h2, h3, l0, l1, l2, l3;
            split_bf16(e0, h0, l0); split_bf16(e1, h1, l1);
            split_bf16(e2, h2, l2); split_bf16(e3, h3, l3);
            size_t o0 = (size_t)rA * N_E + col;
            *(__nv_bfloat162*)&SH[o0]           = __halves2bfloat162(h0, h1);
            *(__nv_bfloat162*)&SL[o0]           = __halves2bfloat162(l0, l1);
            *(__nv_bfloat162*)&SH[o0 + 8 * N_E] = __halves2bfloat162(h2, h3);
            *(__nv_bfloat162*)&SL[o0 + 8 * N_E] = __halves2bfloat162(l2, l3);
        }
    }
#pragma unroll
    for (int mf = 0; mf < 4; mf++) {
#pragma unroll
        for (int rh = 0; rh < 2; rh++) {
            float v = prow[mf][rh];
            v += __shfl_xor_sync(0xffffffffu, v, 1);
            v += __shfl_xor_sync(0xffffffffu, v, 2);
            if ((lid & 3) == 0) {
                int rA = row0 + mw * 64 + mf * 16 + (lid >> 2) + rh * 8;
                atomicAdd(&g_rowsum[h * N_E + rA], v);
            }
        }
    }
}

// ============================================================
// GEMM 3: combine  out[n][h*512+lr] = (1/rowsum[n]) * sum_m w[n][m] * dT[lr][m]
// ============================================================
__global__ __launch_bounds__(256) void combine_gemm(float* __restrict__ out) {
    const int h = blockIdx.z, row0 = blockIdx.y * BM, col0 = blockIdx.x * BN;
    float acc[4][8][4];
    gemm_run(acc, bs_hi  + (size_t)h * N_E * N_E + (size_t)row0 * N_E,
                  bs_lo  + (size_t)h * N_E * N_E + (size_t)row0 * N_E,
                  bdt_hi + (size_t)h * 512 * N_E + (size_t)col0 * N_E,
                  bdt_lo + (size_t)h * 512 * N_E + (size_t)col0 * N_E, N_E, 32);
    const int lid = threadIdx.x & 31, wid = threadIdx.x >> 5;
    const int mw = wid >> 2, nw = wid & 3;
#pragma unroll
    for (int mf = 0; mf < 4; mf++) {
        int row = row0 + mw * 64 + mf * 16 + (lid >> 2);
        float is0 = 1.f / g_rowsum[h * N_E + row];
        float is1 = 1.f / g_rowsum[h * N_E + row + 8];
#pragma unroll
        for (int j = 0; j < 8; j++) {
            int col = col0 + nw * 64 + j * 8 + ((lid & 3) << 1);
            *(float2*)&out[(size_t)row * HLR + h * 512 + col] =
                make_float2(acc[mf][j][0] * is0, acc[mf][j][1] * is0);
            *(float2*)&out[(size_t)(row + 8) * HLR + h * 512 + col] =
                make_float2(acc[mf][j][2] * is1, acc[mf][j][3] * is1);
        }
    }
}

// ============================================================
// converts / small kernels
// ============================================================
__global__ void zero_kernel() {
    int i = blockIdx.x * 256 + threadIdx.x;
    if (i < 3 * N_E) g_sumsq[i] = 0.f;
    if (i < HEAD * N_E) g_rowsum[i] = 0.f;
}

__global__ void rsqrt_kernel() {
    int i = blockIdx.x * 256 + threadIdx.x;
    if (i < 3 * N_E) g_inv[i] = rsqrtf(g_sumsq[i]);
}

__global__ void convert_w_kernel(const float* __restrict__ Wq, const float* __restrict__ Wk,
                                 const float* __restrict__ Wd) {
    int idx = (blockIdx.x * 256 + threadIdx.x) * 4;      // 1536*512 total
    int row = idx >> 9, col = idx & 511;
    const float* src = row < 512 ? Wq : row < 1024 ? Wk : Wd;
    float4 v = *(const float4*)&src[(size_t)(row & 511) * 512 + col];
    __nv_bfloat16 h0, h1, h2, h3, l0, l1, l2, l3;
    split_bf16(v.x, h0, l0); split_bf16(v.y, h1, l1);
    split_bf16(v.z, h2, l2); split_bf16(v.w, h3, l3);
    __nv_bfloat162* dh = (__nv_bfloat162*)&bw_hi[idx];
    __nv_bfloat162* dl = (__nv_bfloat162*)&bw_lo[idx];
    dh[0] = __halves2bfloat162(h0, h1); dh[1] = __halves2bfloat162(h2, h3);
    dl[0] = __halves2bfloat162(l0, l1); dl[1] = __halves2bfloat162(l2, l3);
}

// x[n][f][r] -> xr[n*8+r][f]
__global__ void convert_x_kernel(const float* __restrict__ x) {
    __shared__ float sx[4096];
    const float* xp = x + (size_t)blockIdx.x * 4096;
    for (int i = threadIdx.x; i < 1024; i += 256)
        ((float4*)sx)[i] = ((const float4*)xp)[i];
    __syncthreads();
    for (int i = threadIdx.x; i < 2048; i += 256) {
        int r = i >> 8, f = (i & 255) * 2;
        float a = sx[f * 8 + r], b = sx[f * 8 + 8 + r];
        __nv_bfloat16 ha, hb, la, lb;
        split_bf16(a, ha, la); split_bf16(b, hb, lb);
        size_t o = ((size_t)blockIdx.x * 8 + r) * 512 + f;
        *(__nv_bfloat162*)&bx_hi[o] = __halves2bfloat162(ha, hb);
        *(__nv_bfloat162*)&bx_lo[o] = __halves2bfloat162(la, lb);
    }
}

// bd[h][m][lr] -> bdt[h][lr][m] with inv_d[m] folded; 64x64 tiles
__global__ void convert_d_kernel() {
    __shared__ float tile[64][65];
    const int h = blockIdx.z, j0 = blockIdx.x * 64, m0 = blockIdx.y * 64;
    const int t = threadIdx.x;
    const __nv_bfloat16* SH = bd_hi + (size_t)h * N_E * 512;
    const __nv_bfloat16* SL = bd_lo + (size_t)h * N_E * 512;
#pragma unroll
    for (int i = 0; i < 8; i++) {
        int ml = (t >> 5) + i * 8, m = m0 + ml;
        float inv = g_inv[2 * N_E + m];
        __nv_bfloat162 vh = *(const __nv_bfloat162*)&SH[(size_t)m * 512 + j0 + (t & 31) * 2];
        __nv_bfloat162 vl = *(const __nv_bfloat162*)&SL[(size_t)m * 512 + j0 + (t & 31) * 2];
        tile[ml][(t & 31) * 2]     = (__bfloat162float(vh.x) + __bfloat162float(vl.x)) * inv;
        tile[ml][(t & 31) * 2 + 1] = (__bfloat162float(vh.y) + __bfloat162float(vl.y)) * inv;
    }
    __syncthreads();
#pragma unroll
    for (int i = 0; i < 8; i++) {
        int jl = (t >> 5) + i * 8;
        float v0 = tile[(t & 31) * 2][jl], v1 = tile[(t & 31) * 2 + 1][jl];
        __nv_bfloat16 h0, h1, l0, l1;
        split_bf16(v0, h0, l0); split_bf16(v1, h1, l1);
        size_t o = ((size_t)h * 512 + j0 + jl) * N_E + m0 + (t & 31) * 2;
        *(__nv_bfloat162*)&bdt_hi[o] = __halves2bfloat162(h0, h1);
        *(__nv_bfloat162*)&bdt_lo[o] = __halves2bfloat162(l0, l1);
    }
}

// ============================================================
extern "C" void kernel_launch(void* const* d_in, const int* in_sizes, int n_in,
                              void* d_out, int out_size)
{
    const float* x  = (const float*)d_in[0];
    const float* Wq = (const float*)d_in[1];
    const float* Wk = (const float*)d_in[2];
    const float* Wd = (const float*)d_in[3];
    float* out = (float*)d_out;

    cudaFuncSetAttribute(proj_gemm,    cudaFuncAttributeMaxDynamicSharedMemorySize, SMEM_DYN);
    cudaFuncSetAttribute(scores_gemm,  cudaFuncAttributeMaxDynamicSharedMemorySize, SMEM_DYN);
    cudaFuncSetAttribute(combine_gemm, cudaFuncAttributeMaxDynamicSharedMemorySize, SMEM_DYN);

    zero_kernel<<<64, 256>>>();
    convert_w_kernel<<<768, 256>>>(Wq, Wk, Wd);
    convert_x_kernel<<<N_E, 256>>>(x);
    proj_gemm<<<dim3(64, 12), 256, SMEM_DYN>>>();
    rsqrt_kernel<<<24, 256>>>();
    convert_d_kernel<<<dim3(8, 32, HEAD), 256>>>();
    scores_gemm<<<dim3(8, 16, HEAD), 256, SMEM_DYN>>>();
    combine_gemm<<<dim3(2, 16, HEAD), 256, SMEM_DYN>>>(out);
}

// round 13
// speedup vs baseline: 1.6109x; 1.6109x over previous
#include <cuda_runtime.h>
#include <cuda_fp16.h>
#include <math.h>
#include <stdint.h>

#define N_E   2048
#define HEAD  8
#define HLR   4096

// ---------------- small fp32 scratch ----------------
__device__ float g_sumsq[3 * N_E];
__device__ float g_inv[3 * N_E];            // rsqrt norms (q,k,d)
__device__ float g_rowsum[HEAD * N_E];      // softmax denominators

// ---------------- fp16 operands (2-pass: A-side keeps lo, B-side hi only) ----------------
__device__ __half bx_hi[(size_t)16384 * 512];        // xr[n*8+r][f]        (B of proj)
__device__ __half bw_hi[(size_t)1536 * 512];         // W concat [hq'][f]   (A of proj)
__device__ __half bw_lo[(size_t)1536 * 512];
__device__ __half bq_hi[(size_t)HEAD * N_E * 512];   // q [h][n][lr]        (A of scores)
__device__ __half bq_lo[(size_t)HEAD * N_E * 512];
__device__ __half bk_hi[(size_t)HEAD * N_E * 512];   // k                   (B of scores)
__device__ __half bd_hi[(size_t)HEAD * N_E * 512];   // d (pre-transpose, needs hi+lo for accurate dT)
__device__ __half bd_lo[(size_t)HEAD * N_E * 512];
__device__ __half bs_hi[(size_t)HEAD * N_E * N_E];   // exp-weights [h][n][m] (A of combine)
__device__ __half bs_lo[(size_t)HEAD * N_E * N_E];
__device__ __half bdt_hi[(size_t)HEAD * 512 * N_E];  // dT [h][lr][m], inv_d folded (B of combine)

// ---------------- warp-MMA GEMM core: 128x256x64, 8 warps (2x4), warp tile 64x64 ----------------
// Fused 2-pass: per k-tile, B resident once; MMA with A_hi then A_lo.
#define BM 128
#define BN 256
#define BK 64
#define STG 3
#define SA_BYTES (BM * 128)                    // 16384 per A buffer
#define SB_BYTES (BN * 128)                    // 32768
#define STAGE_BYTES (2 * SA_BYTES + SB_BYTES)  // 65536
#define SMEM_DYN (STG * STAGE_BYTES)           // 196608

__device__ __forceinline__ void cp16(uint32_t s, const void* g) {
    asm volatile("cp.async.cg.shared.global [%0], [%1], 16;\n"
                 :: "r"(s), "l"(__cvta_generic_to_global(g)));
}
__device__ __forceinline__ void cp_commit() { asm volatile("cp.async.commit_group;\n" ::: "memory"); }
__device__ __forceinline__ void cp_wait1()  { asm volatile("cp.async.wait_group 1;\n" ::: "memory"); }

__device__ __forceinline__ void ldsm4(uint32_t* r, uint32_t a) {
    asm volatile("ldmatrix.sync.aligned.m8n8.x4.shared.b16 {%0,%1,%2,%3}, [%4];"
                 : "=r"(r[0]), "=r"(r[1]), "=r"(r[2]), "=r"(r[3]) : "r"(a));
}
__device__ __forceinline__ void mma16816(float* c, const uint32_t* a, const uint32_t* b) {
    asm volatile("mma.sync.aligned.m16n8k16.row.col.f32.f16.f16.f32 "
                 "{%0,%1,%2,%3}, {%4,%5,%6,%7}, {%8,%9}, {%0,%1,%2,%3};"
                 : "+f"(c[0]), "+f"(c[1]), "+f"(c[2]), "+f"(c[3])
                 : "r"(a[0]), "r"(a[1]), "r"(a[2]), "r"(a[3]), "r"(b[0]), "r"(b[1]));
}

// one stage: A_hi 128x64, A_lo 128x64, B 256x64 (fp16), 128B rows, unit-XOR swizzle
__device__ __forceinline__ void load_stage(uint32_t s,
                                           const __half* __restrict__ Ahi,
                                           const __half* __restrict__ Alo,
                                           const __half* __restrict__ B, int ldk) {
    const int tid = threadIdx.x;
#pragma unroll
    for (int i = 0; i < 4; i++) {
        int idx = tid + i * 256, r = idx >> 3, c = idx & 7;
        uint32_t d = r * 128 + ((c ^ (r & 7)) << 4);
        cp16(s + d, Ahi + (size_t)r * ldk + c * 8);
        cp16(s + SA_BYTES + d, Alo + (size_t)r * ldk + c * 8);
    }
#pragma unroll
    for (int i = 0; i < 8; i++) {
        int idx = tid + i * 256, r = idx >> 3, c = idx & 7;
        cp16(s + 2 * SA_BYTES + r * 128 + ((c ^ (r & 7)) << 4), B + (size_t)r * ldk + c * 8);
    }
    cp_commit();
}

// fused 2-pass mainloop over KT k-tiles
__device__ __forceinline__ void gemm_run(float (&acc)[4][8][4],
    const __half* __restrict__ Ahi, const __half* __restrict__ Alo,
    const __half* __restrict__ B, const int ldk, const int KT)
{
    extern __shared__ char smem[];
    const uint32_t sb = (uint32_t)__cvta_generic_to_shared(smem);
    const int tid = threadIdx.x, lid = tid & 31, wid = tid >> 5;
    const int mw = wid >> 2, nw = wid & 3;

#pragma unroll
    for (int mf = 0; mf < 4; mf++)
#pragma unroll
        for (int j = 0; j < 8; j++)
#pragma unroll
            for (int e = 0; e < 4; e++) acc[mf][j][e] = 0.f;

    int rowA[4], rowB[4];
#pragma unroll
    for (int mf = 0; mf < 4; mf++)
        rowA[mf] = mw * 64 + mf * 16 + ((lid >> 3) & 1) * 8 + (lid & 7);
#pragma unroll
    for (int nf = 0; nf < 4; nf++)
        rowB[nf] = nw * 64 + nf * 16 + (lid >> 4) * 8 + (lid & 7);
    const int uhA = lid >> 4;
    const int uB  = (lid >> 3) & 1;

#pragma unroll
    for (int s = 0; s < STG - 1; s++)
        load_stage(sb + s * STAGE_BYTES, Ahi + (size_t)s * BK, Alo + (size_t)s * BK,
                   B + (size_t)s * BK, ldk);

    for (int t = 0; t < KT; t++) {
        cp_wait1();
        __syncthreads();
        int tn = t + STG - 1;
        if (tn < KT) {
            load_stage(sb + (tn % STG) * STAGE_BYTES, Ahi + (size_t)tn * BK,
                       Alo + (size_t)tn * BK, B + (size_t)tn * BK, ldk);
        } else {
            cp_commit();
        }
        const uint32_t sA = sb + (t % STG) * STAGE_BYTES;
        const uint32_t sL = sA + SA_BYTES;
        const uint32_t sB = sA + 2 * SA_BYTES;
#pragma unroll
        for (int ks = 0; ks < 4; ks++) {
            uint32_t ah[4][4], al[4][4], b[4][4];
#pragma unroll
            for (int mf = 0; mf < 4; mf++) {
                uint32_t off = rowA[mf] * 128 + (((ks * 2 + uhA) ^ (rowA[mf] & 7)) << 4);
                ldsm4(ah[mf], sA + off);
                ldsm4(al[mf], sL + off);
            }
#pragma unroll
            for (int nf = 0; nf < 4; nf++)
                ldsm4(b[nf], sB + rowB[nf] * 128 + (((ks * 2 + uB) ^ (rowB[nf] & 7)) << 4));
#pragma unroll
            for (int mf = 0; mf < 4; mf++)
#pragma unroll
                for (int nf = 0; nf < 4; nf++) {
                    mma16816(acc[mf][nf * 2],     ah[mf], &b[nf][0]);
                    mma16816(acc[mf][nf * 2 + 1], ah[mf], &b[nf][2]);
                }
#pragma unroll
            for (int mf = 0; mf < 4; mf++)
#pragma unroll
                for (int nf = 0; nf < 4; nf++) {
                    mma16816(acc[mf][nf * 2],     al[mf], &b[nf][0]);
                    mma16816(acc[mf][nf * 2 + 1], al[mf], &b[nf][2]);
                }
        }
    }
}

__device__ __forceinline__ void split_f16(float v, __half& hi, __half& lo) {
    hi = __float2half_rn(v);
    lo = __float2half_rn(v - __half2float(hi));
}

// ============================================================
// GEMM 1: proj  C[hq'(1536)][c(16384)] = Wcat . xr^T
// epilogue: fp16 scatter (q: hi+lo, k: hi, d: hi+lo) + per-n sumsq atomics
// ============================================================
__global__ __launch_bounds__(256) void proj_gemm() {
    const int row0 = blockIdx.y * BM, col0 = blockIdx.x * BN;
    float acc[4][8][4];
    gemm_run(acc, bw_hi + (size_t)row0 * 512, bw_lo + (size_t)row0 * 512,
                  bx_hi + (size_t)col0 * 512, 512, 8);
    const int lid = threadIdx.x & 31, wid = threadIdx.x >> 5;
    const int mw = wid >> 2, nw = wid & 3;
    const int which = row0 >> 9;                         // 0=q,1=k,2=d
    __half* DH = (which == 0) ? bq_hi : (which == 1) ? bk_hi : bd_hi;
    __half* DL = (which == 0) ? bq_lo : bd_lo;           // unused when which==1
    const bool need_lo = (which != 1);

    float psum[8];
#pragma unroll
    for (int j = 0; j < 8; j++) psum[j] = 0.f;

#pragma unroll
    for (int mf = 0; mf < 4; mf++) {
        int row = row0 + mw * 64 + mf * 16 + (lid >> 2);
        int hq = row & 511, h = hq >> 6, ql = hq & 63;
#pragma unroll
        for (int j = 0; j < 8; j++) {
            int col = col0 + nw * 64 + j * 8 + ((lid & 3) << 1);
            int n = col >> 3, r = col & 7;
            float v0 = acc[mf][j][0], v1 = acc[mf][j][1];
            float v2 = acc[mf][j][2], v3 = acc[mf][j][3];
            psum[j] += v0 * v0 + v1 * v1 + v2 * v2 + v3 * v3;
            size_t o0 = ((size_t)(h * N_E + n)) * 512 + ql * 8 + r;
            __half h0, h1, h2, h3, l0, l1, l2, l3;
            split_f16(v0, h0, l0); split_f16(v1, h1, l1);
            split_f16(v2, h2, l2); split_f16(v3, h3, l3);
            *(__half2*)&DH[o0]      = __halves2half2(h0, h1);
            *(__half2*)&DH[o0 + 64] = __halves2half2(h2, h3);       // row ql+8
            if (need_lo) {
                *(__half2*)&DL[o0]      = __halves2half2(l0, l1);
                *(__half2*)&DL[o0 + 64] = __halves2half2(l2, l3);
            }
        }
    }
#pragma unroll
    for (int j = 0; j < 8; j++) {
#pragma unroll
        for (int o = 16; o; o >>= 1) psum[j] += __shfl_xor_sync(0xffffffffu, psum[j], o);
    }
    if (lid == 0) {
        int nb = (col0 >> 3) + nw * 8;
#pragma unroll
        for (int j = 0; j < 8; j++)
            atomicAdd(&g_sumsq[which * N_E + nb + j], psum[j]);
    }
}

// ============================================================
// GEMM 2: scores -> exp-weights.  logit = (q.k)*inv_q[n]*inv_k[m], |logit|<=1
// epilogue: w = exp(logit) -> fp16 hi+lo + row-sum atomics
// ============================================================
__global__ __launch_bounds__(256) void scores_gemm() {
    const int h = blockIdx.z, row0 = blockIdx.y * BM, col0 = blockIdx.x * BN;
    const size_t ho = (size_t)h * N_E * 512;
    float acc[4][8][4];
    gemm_run(acc, bq_hi + ho + (size_t)row0 * 512, bq_lo + ho + (size_t)row0 * 512,
                  bk_hi + ho + (size_t)col0 * 512, 512, 8);
    const int lid = threadIdx.x & 31, wid = threadIdx.x >> 5;
    const int mw = wid >> 2, nw = wid & 3;
    __half* SH = bs_hi + (size_t)h * N_E * N_E;
    __half* SL = bs_lo + (size_t)h * N_E * N_E;

    float prow[4][2];
#pragma unroll
    for (int mf = 0; mf < 4; mf++) { prow[mf][0] = 0.f; prow[mf][1] = 0.f; }

#pragma unroll
    for (int mf = 0; mf < 4; mf++) {
        int rA = row0 + mw * 64 + mf * 16 + (lid >> 2);
        float iq0 = g_inv[rA], iq1 = g_inv[rA + 8];
#pragma unroll
        for (int j = 0; j < 8; j++) {
            int col = col0 + nw * 64 + j * 8 + ((lid & 3) << 1);
            float ik0 = g_inv[N_E + col], ik1 = g_inv[N_E + col + 1];
            float e0 = __expf(acc[mf][j][0] * iq0 * ik0);
            float e1 = __expf(acc[mf][j][1] * iq0 * ik1);
            float e2 = __expf(acc[mf][j][2] * iq1 * ik0);
            float e3 = __expf(acc[mf][j][3] * iq1 * ik1);
            prow[mf][0] += e0 + e1;
            prow[mf][1] += e2 + e3;
            __half h0, h1, h2, h3, l0, l1, l2, l3;
            split_f16(e0, h0, l0); split_f16(e1, h1, l1);
            split_f16(e2, h2, l2); split_f16(e3, h3, l3);
            size_t o0 = (size_t)rA * N_E + col;
            *(__half2*)&SH[o0]           = __halves2half2(h0, h1);
            *(__half2*)&SL[o0]           = __halves2half2(l0, l1);
            *(__half2*)&SH[o0 + 8 * N_E] = __halves2half2(h2, h3);
            *(__half2*)&SL[o0 + 8 * N_E] = __halves2half2(l2, l3);
        }
    }
#pragma unroll
    for (int mf = 0; mf < 4; mf++) {
#pragma unroll
        for (int rh = 0; rh < 2; rh++) {
            float v = prow[mf][rh];
            v += __shfl_xor_sync(0xffffffffu, v, 1);
            v += __shfl_xor_sync(0xffffffffu, v, 2);
            if ((lid & 3) == 0) {
                int rA = row0 + mw * 64 + mf * 16 + (lid >> 2) + rh * 8;
                atomicAdd(&g_rowsum[h * N_E + rA], v);
            }
        }
    }
}

// ============================================================
// GEMM 3: combine  out[n][h*512+lr] = (1/rowsum[n]) * sum_m w[n][m] * dT[lr][m]
// ============================================================
__global__ __launch_bounds__(256) void combine_gemm(float* __restrict__ out) {
    const int h = blockIdx.z, row0 = blockIdx.y * BM, col0 = blockIdx.x * BN;
    float acc[4][8][4];
    gemm_run(acc, bs_hi  + (size_t)h * N_E * N_E + (size_t)row0 * N_E,
                  bs_lo  + (size_t)h * N_E * N_E + (size_t)row0 * N_E,
                  bdt_hi + (size_t)h * 512 * N_E + (size_t)col0 * N_E, N_E, 32);
    const int lid = threadIdx.x & 31, wid = threadIdx.x >> 5;
    const int mw = wid >> 2, nw = wid & 3;
#pragma unroll
    for (int mf = 0; mf < 4; mf++) {
        int row = row0 + mw * 64 + mf * 16 + (lid >> 2);
        float is0 = 1.f / g_rowsum[h * N_E + row];
        float is1 = 1.f / g_rowsum[h * N_E + row + 8];
#pragma unroll
        for (int j = 0; j < 8; j++) {
            int col = col0 + nw * 64 + j * 8 + ((lid & 3) << 1);
            *(float2*)&out[(size_t)row * HLR + h * 512 + col] =
                make_float2(acc[mf][j][0] * is0, acc[mf][j][1] * is0);
            *(float2*)&out[(size_t)(row + 8) * HLR + h * 512 + col] =
                make_float2(acc[mf][j][2] * is1, acc[mf][j][3] * is1);
        }
    }
}

// ============================================================
// converts / small kernels
// ============================================================
__global__ void zero_kernel() {
    int i = blockIdx.x * 256 + threadIdx.x;
    if (i < 3 * N_E) g_sumsq[i] = 0.f;
    if (i < HEAD * N_E) g_rowsum[i] = 0.f;
}

__global__ void rsqrt_kernel() {
    int i = blockIdx.x * 256 + threadIdx.x;
    if (i < 3 * N_E) g_inv[i] = rsqrtf(g_sumsq[i]);
}

__global__ void convert_w_kernel(const float* __restrict__ Wq, const float* __restrict__ Wk,
                                 const float* __restrict__ Wd) {
    int idx = (blockIdx.x * 256 + threadIdx.x) * 4;      // 1536*512 total
    int row = idx >> 9, col = idx & 511;
    const float* src = row < 512 ? Wq : row < 1024 ? Wk : Wd;
    float4 v = *(const float4*)&src[(size_t)(row & 511) * 512 + col];
    __half h0, h1, h2, h3, l0, l1, l2, l3;
    split_f16(v.x, h0, l0); split_f16(v.y, h1, l1);
    split_f16(v.z, h2, l2); split_f16(v.w, h3, l3);
    __half2* dh = (__half2*)&bw_hi[idx];
    __half2* dl = (__half2*)&bw_lo[idx];
    dh[0] = __halves2half2(h0, h1); dh[1] = __halves2half2(h2, h3);
    dl[0] = __halves2half2(l0, l1); dl[1] = __halves2half2(l2, l3);
}

// x[n][f][r] -> xr[n*8+r][f], hi only (B-side of proj)
__global__ void convert_x_kernel(const float* __restrict__ x) {
    __shared__ float sx[4096];
    const float* xp = x + (size_t)blockIdx.x * 4096;
    for (int i = threadIdx.x; i < 1024; i += 256)
        ((float4*)sx)[i] = ((const float4*)xp)[i];
    __syncthreads();
    for (int i = threadIdx.x; i < 2048; i += 256) {
        int r = i >> 8, f = (i & 255) * 2;
        float a = sx[f * 8 + r], b = sx[f * 8 + 8 + r];
        size_t o = ((size_t)blockIdx.x * 8 + r) * 512 + f;
        *(__half2*)&bx_hi[o] = __halves2half2(__float2half_rn(a), __float2half_rn(b));
    }
}

// bd[h][m][lr] (hi+lo) -> bdt[h][lr][m] hi-only with inv_d[m] folded; 64x64 tiles
__global__ void convert_d_kernel() {
    __shared__ float tile[64][65];
    const int h = blockIdx.z, j0 = blockIdx.x * 64, m0 = blockIdx.y * 64;
    const int t = threadIdx.x;
    const __half* SH = bd_hi + (size_t)h * N_E * 512;
    const __half* SL = bd_lo + (size_t)h * N_E * 512;
#pragma unroll
    for (int i = 0; i < 8; i++) {
        int ml = (t >> 5) + i * 8, m = m0 + ml;
        float inv = g_inv[2 * N_E + m];
        __half2 vh = *(const __half2*)&SH[(size_t)m * 512 + j0 + (t & 31) * 2];
        __half2 vl = *(const __half2*)&SL[(size_t)m * 512 + j0 + (t & 31) * 2];
        tile[ml][(t & 31) * 2]     = (__half2float(vh.x) + __half2float(vl.x)) * inv;
        tile[ml][(t & 31) * 2 + 1] = (__half2float(vh.y) + __half2float(vl.y)) * inv;
    }
    __syncthreads();
#pragma unroll
    for (int i = 0; i < 8; i++) {
        int jl = (t >> 5) + i * 8;
        float v0 = tile[(t & 31) * 2][jl], v1 = tile[(t & 31) * 2 + 1][jl];
        size_t o = ((size_t)h * 512 + j0 + jl) * N_E + m0 + (t & 31) * 2;
        *(__half2*)&bdt_hi[o] = __halves2half2(__float2half_rn(v0), __float2half_rn(v1));
    }
}

// ============================================================
extern "C" void kernel_launch(void* const* d_in, const int* in_sizes, int n_in,
                              void* d_out, int out_size)
{
    const float* x  = (const float*)d_in[0];
    const float* Wq = (const float*)d_in[1];
    const float* Wk = (const float*)d_in[2];
    const float* Wd = (const float*)d_in[3];
    float* out = (float*)d_out;

    cudaFuncSetAttribute(proj_gemm,    cudaFuncAttributeMaxDynamicSharedMemorySize, SMEM_DYN);
    cudaFuncSetAttribute(scores_gemm,  cudaFuncAttributeMaxDynamicSharedMemorySize, SMEM_DYN);
    cudaFuncSetAttribute(combine_gemm, cudaFuncAttributeMaxDynamicSharedMemorySize, SMEM_DYN);

    zero_kernel<<<64, 256>>>();
    convert_w_kernel<<<768, 256>>>(Wq, Wk, Wd);
    convert_x_kernel<<<N_E, 256>>>(x);
    proj_gemm<<<dim3(64, 12), 256, SMEM_DYN>>>();
    rsqrt_kernel<<<24, 256>>>();
    convert_d_kernel<<<dim3(8, 32, HEAD), 256>>>();
    scores_gemm<<<dim3(8, 16, HEAD), 256, SMEM_DYN>>>();
    combine_gemm<<<dim3(2, 16, HEAD), 256, SMEM_DYN>>>(out);
}

// round 14
// speedup vs baseline: 2.5794x; 1.6012x over previous
#include <cuda_runtime.h>
#include <cuda_fp16.h>
#include <math.h>
#include <stdint.h>

#define N_E   2048
#define HEAD  8
#define HLR   4096

// ---------------- small fp32 scratch ----------------
__device__ float g_sumsq[3 * N_E];
__device__ float g_inv[3 * N_E];            // rsqrt norms (q,k,d)
__device__ float g_rowsum[HEAD * N_E];      // softmax denominators

// ---------------- fp16 operands (1-pass) ----------------
__device__ __half bx_hi[(size_t)16384 * 512];        // xr[n*8+r][f]        (B of proj)
__device__ __half bw_hi[(size_t)1536 * 512];         // W concat [hq'][f]   (A of proj)
__device__ __half bq_hi[(size_t)HEAD * N_E * 512];   // q [h][n][lr]        (A of scores)
__device__ __half bk_hi[(size_t)HEAD * N_E * 512];   // k                   (B of scores)
__device__ __half bd_hi[(size_t)HEAD * N_E * 512];   // d pre-transpose (hi+lo for accurate dT)
__device__ __half bd_lo[(size_t)HEAD * N_E * 512];
__device__ __half bs_hi[(size_t)HEAD * N_E * N_E];   // exp-weights [h][n][m] (A of combine)
__device__ __half bdt_hi[(size_t)HEAD * 512 * N_E];  // dT [h][lr][m], inv_d folded (B of combine)

// ---------------- warp-MMA GEMM core: 128x256x128, 8 warps (2x4), warp tile 64x64 ----------------
#define BM 128
#define BN 256
#define BK 128
#define SA_BYTES (BM * 256)                    // 32768  (256B rows: BK*2)
#define SB_BYTES (BN * 256)                    // 65536
#define STAGE_BYTES (SA_BYTES + SB_BYTES)      // 98304
#define SMEM_DYN (2 * STAGE_BYTES)             // 196608

__device__ __forceinline__ void cp16(uint32_t s, const void* g) {
    asm volatile("cp.async.cg.shared.global [%0], [%1], 16;\n"
                 :: "r"(s), "l"(__cvta_generic_to_global(g)));
}
__device__ __forceinline__ void cp_commit() { asm volatile("cp.async.commit_group;\n" ::: "memory"); }
__device__ __forceinline__ void cp_wait1()  { asm volatile("cp.async.wait_group 1;\n" ::: "memory"); }

__device__ __forceinline__ void ldsm4(uint32_t* r, uint32_t a) {
    asm volatile("ldmatrix.sync.aligned.m8n8.x4.shared.b16 {%0,%1,%2,%3}, [%4];"
                 : "=r"(r[0]), "=r"(r[1]), "=r"(r[2]), "=r"(r[3]) : "r"(a));
}
__device__ __forceinline__ void mma16816(float* c, const uint32_t* a, const uint32_t* b) {
    asm volatile("mma.sync.aligned.m16n8k16.row.col.f32.f16.f16.f32 "
                 "{%0,%1,%2,%3}, {%4,%5,%6,%7}, {%8,%9}, {%0,%1,%2,%3};"
                 : "+f"(c[0]), "+f"(c[1]), "+f"(c[2]), "+f"(c[3])
                 : "r"(a[0]), "r"(a[1]), "r"(a[2]), "r"(a[3]), "r"(b[0]), "r"(b[1]));
}

// one stage: A 128x128 fp16 (32KB), B 256x128 fp16 (64KB); 256B rows, XOR-on-low-3-bit swizzle
__device__ __forceinline__ void load_stage(uint32_t s,
                                           const __half* __restrict__ A,
                                           const __half* __restrict__ B, int ldk) {
    const int tid = threadIdx.x;
#pragma unroll
    for (int i = 0; i < 8; i++) {                       // A: 2048 16B units
        int idx = tid + i * 256, r = idx >> 4, c = idx & 15;
        cp16(s + r * 256 + ((c ^ (r & 7)) << 4), A + (size_t)r * ldk + c * 8);
    }
#pragma unroll
    for (int i = 0; i < 16; i++) {                      // B: 4096 16B units
        int idx = tid + i * 256, r = idx >> 4, c = idx & 15;
        cp16(s + SA_BYTES + r * 256 + ((c ^ (r & 7)) << 4), B + (size_t)r * ldk + c * 8);
    }
    cp_commit();
}

// 1-pass fp16 mainloop over KT k-tiles of 128, 2-stage
__device__ __forceinline__ void gemm_run(float (&acc)[4][8][4],
    const __half* __restrict__ A, const __half* __restrict__ B,
    const int ldk, const int KT)
{
    extern __shared__ char smem[];
    const uint32_t sb = (uint32_t)__cvta_generic_to_shared(smem);
    const int tid = threadIdx.x, lid = tid & 31, wid = tid >> 5;
    const int mw = wid >> 2, nw = wid & 3;

#pragma unroll
    for (int mf = 0; mf < 4; mf++)
#pragma unroll
        for (int j = 0; j < 8; j++)
#pragma unroll
            for (int e = 0; e < 4; e++) acc[mf][j][e] = 0.f;

    int rowA[4], rowB[4];
#pragma unroll
    for (int mf = 0; mf < 4; mf++)
        rowA[mf] = mw * 64 + mf * 16 + ((lid >> 3) & 1) * 8 + (lid & 7);
#pragma unroll
    for (int nf = 0; nf < 4; nf++)
        rowB[nf] = nw * 64 + nf * 16 + (lid >> 4) * 8 + (lid & 7);
    const int uhA = lid >> 4;
    const int uB  = (lid >> 3) & 1;

    load_stage(sb, A, B, ldk);                           // stage 0, tile 0

    for (int t = 0; t < KT; t++) {
        // issue next tile into the other stage (computed 2 iters ago; tail barrier protects it)
        if (t + 1 < KT)
            load_stage(sb + ((t + 1) & 1) * STAGE_BYTES,
                       A + (size_t)(t + 1) * BK, B + (size_t)(t + 1) * BK, ldk);
        else
            cp_commit();                                  // empty group keeps wait-count math uniform
        cp_wait1();                                       // tile t resident
        __syncthreads();

        const uint32_t sA = sb + (t & 1) * STAGE_BYTES;
        const uint32_t sB = sA + SA_BYTES;
#pragma unroll
        for (int ks = 0; ks < 8; ks++) {
            uint32_t a[4][4], b[4][4];
#pragma unroll
            for (int mf = 0; mf < 4; mf++)
                ldsm4(a[mf], sA + rowA[mf] * 256 + (((ks * 2 + uhA) ^ (rowA[mf] & 7)) << 4));
#pragma unroll
            for (int nf = 0; nf < 4; nf++)
                ldsm4(b[nf], sB + rowB[nf] * 256 + (((ks * 2 + uB) ^ (rowB[nf] & 7)) << 4));
#pragma unroll
            for (int mf = 0; mf < 4; mf++)
#pragma unroll
                for (int nf = 0; nf < 4; nf++) {
                    mma16816(acc[mf][nf * 2],     a[mf], &b[nf][0]);
                    mma16816(acc[mf][nf * 2 + 1], a[mf], &b[nf][2]);
                }
        }
        __syncthreads();                                  // stage t fully consumed before overwrite
    }
}

__device__ __forceinline__ void split_f16(float v, __half& hi, __half& lo) {
    hi = __float2half_rn(v);
    lo = __float2half_rn(v - __half2float(hi));
}

// ============================================================
// GEMM 1: proj  C[hq'(1536)][c(16384)] = Wcat . xr^T
// epilogue: fp16 scatter (q: hi, k: hi, d: hi+lo) + per-n sumsq atomics
// ============================================================
__global__ __launch_bounds__(256) void proj_gemm() {
    const int row0 = blockIdx.y * BM, col0 = blockIdx.x * BN;
    float acc[4][8][4];
    gemm_run(acc, bw_hi + (size_t)row0 * 512, bx_hi + (size_t)col0 * 512, 512, 4);
    const int lid = threadIdx.x & 31, wid = threadIdx.x >> 5;
    const int mw = wid >> 2, nw = wid & 3;
    const int which = row0 >> 9;                         // 0=q,1=k,2=d
    __half* DH = (which == 0) ? bq_hi : (which == 1) ? bk_hi : bd_hi;
    const bool need_lo = (which == 2);

    float psum[8];
#pragma unroll
    for (int j = 0; j < 8; j++) psum[j] = 0.f;

#pragma unroll
    for (int mf = 0; mf < 4; mf++) {
        int row = row0 + mw * 64 + mf * 16 + (lid >> 2);
        int hq = row & 511, h = hq >> 6, ql = hq & 63;
#pragma unroll
        for (int j = 0; j < 8; j++) {
            int col = col0 + nw * 64 + j * 8 + ((lid & 3) << 1);
            int n = col >> 3, r = col & 7;
            float v0 = acc[mf][j][0], v1 = acc[mf][j][1];
            float v2 = acc[mf][j][2], v3 = acc[mf][j][3];
            psum[j] += v0 * v0 + v1 * v1 + v2 * v2 + v3 * v3;
            size_t o0 = ((size_t)(h * N_E + n)) * 512 + ql * 8 + r;
            __half h0, h1, h2, h3, l0, l1, l2, l3;
            split_f16(v0, h0, l0); split_f16(v1, h1, l1);
            split_f16(v2, h2, l2); split_f16(v3, h3, l3);
            *(__half2*)&DH[o0]      = __halves2half2(h0, h1);
            *(__half2*)&DH[o0 + 64] = __halves2half2(h2, h3);       // row ql+8
            if (need_lo) {
                *(__half2*)&bd_lo[o0]      = __halves2half2(l0, l1);
                *(__half2*)&bd_lo[o0 + 64] = __halves2half2(l2, l3);
            }
        }
    }
#pragma unroll
    for (int j = 0; j < 8; j++) {
#pragma unroll
        for (int o = 16; o; o >>= 1) psum[j] += __shfl_xor_sync(0xffffffffu, psum[j], o);
    }
    if (lid == 0) {
        int nb = (col0 >> 3) + nw * 8;
#pragma unroll
        for (int j = 0; j < 8; j++)
            atomicAdd(&g_sumsq[which * N_E + nb + j], psum[j]);
    }
}

// ============================================================
// GEMM 2: scores -> exp-weights.  logit = (q.k)*inv_q[n]*inv_k[m], |logit|<=1
// epilogue: w = exp(logit) -> fp16 + row-sum atomics
// ============================================================
__global__ __launch_bounds__(256) void scores_gemm() {
    const int h = blockIdx.z, row0 = blockIdx.y * BM, col0 = blockIdx.x * BN;
    const size_t ho = (size_t)h * N_E * 512;
    float acc[4][8][4];
    gemm_run(acc, bq_hi + ho + (size_t)row0 * 512, bk_hi + ho + (size_t)col0 * 512, 512, 4);
    const int lid = threadIdx.x & 31, wid = threadIdx.x >> 5;
    const int mw = wid >> 2, nw = wid & 3;
    __half* SH = bs_hi + (size_t)h * N_E * N_E;

    float prow[4][2];
#pragma unroll
    for (int mf = 0; mf < 4; mf++) { prow[mf][0] = 0.f; prow[mf][1] = 0.f; }

#pragma unroll
    for (int mf = 0; mf < 4; mf++) {
        int rA = row0 + mw * 64 + mf * 16 + (lid >> 2);
        float iq0 = g_inv[rA], iq1 = g_inv[rA + 8];
#pragma unroll
        for (int j = 0; j < 8; j++) {
            int col = col0 + nw * 64 + j * 8 + ((lid & 3) << 1);
            float ik0 = g_inv[N_E + col], ik1 = g_inv[N_E + col + 1];
            float e0 = __expf(acc[mf][j][0] * iq0 * ik0);
            float e1 = __expf(acc[mf][j][1] * iq0 * ik1);
            float e2 = __expf(acc[mf][j][2] * iq1 * ik0);
            float e3 = __expf(acc[mf][j][3] * iq1 * ik1);
            prow[mf][0] += e0 + e1;
            prow[mf][1] += e2 + e3;
            size_t o0 = (size_t)rA * N_E + col;
            *(__half2*)&SH[o0]           = __halves2half2(__float2half_rn(e0), __float2half_rn(e1));
            *(__half2*)&SH[o0 + 8 * N_E] = __halves2half2(__float2half_rn(e2), __float2half_rn(e3));
        }
    }
#pragma unroll
    for (int mf = 0; mf < 4; mf++) {
#pragma unroll
        for (int rh = 0; rh < 2; rh++) {
            float v = prow[mf][rh];
            v += __shfl_xor_sync(0xffffffffu, v, 1);
            v += __shfl_xor_sync(0xffffffffu, v, 2);
            if ((lid & 3) == 0) {
                int rA = row0 + mw * 64 + mf * 16 + (lid >> 2) + rh * 8;
                atomicAdd(&g_rowsum[h * N_E + rA], v);
            }
        }
    }
}

// ============================================================
// GEMM 3: combine  out[n][h*512+lr] = (1/rowsum[n]) * sum_m w[n][m] * dT[lr][m]
// ============================================================
__global__ __launch_bounds__(256) void combine_gemm(float* __restrict__ out) {
    const int h = blockIdx.z, row0 = blockIdx.y * BM, col0 = blockIdx.x * BN;
    float acc[4][8][4];
    gemm_run(acc, bs_hi  + (size_t)h * N_E * N_E + (size_t)row0 * N_E,
                  bdt_hi + (size_t)h * 512 * N_E + (size_t)col0 * N_E, N_E, 16);
    const int lid = threadIdx.x & 31, wid = threadIdx.x >> 5;
    const int mw = wid >> 2, nw = wid & 3;
#pragma unroll
    for (int mf = 0; mf < 4; mf++) {
        int row = row0 + mw * 64 + mf * 16 + (lid >> 2);
        float is0 = 1.f / g_rowsum[h * N_E + row];
        float is1 = 1.f / g_rowsum[h * N_E + row + 8];
#pragma unroll
        for (int j = 0; j < 8; j++) {
            int col = col0 + nw * 64 + j * 8 + ((lid & 3) << 1);
            *(float2*)&out[(size_t)row * HLR + h * 512 + col] =
                make_float2(acc[mf][j][0] * is0, acc[mf][j][1] * is0);
            *(float2*)&out[(size_t)(row + 8) * HLR + h * 512 + col] =
                make_float2(acc[mf][j][2] * is1, acc[mf][j][3] * is1);
        }
    }
}

// ============================================================
// converts / small kernels
// ============================================================
__global__ void zero_kernel() {
    int i = blockIdx.x * 256 + threadIdx.x;
    if (i < 3 * N_E) g_sumsq[i] = 0.f;
    if (i < HEAD * N_E) g_rowsum[i] = 0.f;
}

__global__ void rsqrt_kernel() {
    int i = blockIdx.x * 256 + threadIdx.x;
    if (i < 3 * N_E) g_inv[i] = rsqrtf(g_sumsq[i]);
}

__global__ void convert_w_kernel(const float* __restrict__ Wq, const float* __restrict__ Wk,
                                 const float* __restrict__ Wd) {
    int idx = (blockIdx.x * 256 + threadIdx.x) * 4;      // 1536*512 total
    int row = idx >> 9, col = idx & 511;
    const float* src = row < 512 ? Wq : row < 1024 ? Wk : Wd;
    float4 v = *(const float4*)&src[(size_t)(row & 511) * 512 + col];
    __half2* dh = (__half2*)&bw_hi[idx];
    dh[0] = __halves2half2(__float2half_rn(v.x), __float2half_rn(v.y));
    dh[1] = __halves2half2(__float2half_rn(v.z), __float2half_rn(v.w));
}

// x[n][f][r] -> xr[n*8+r][f]
__global__ void convert_x_kernel(const float* __restrict__ x) {
    __shared__ float sx[4096];
    const float* xp = x + (size_t)blockIdx.x * 4096;
    for (int i = threadIdx.x; i < 1024; i += 256)
        ((float4*)sx)[i] = ((const float4*)xp)[i];
    __syncthreads();
    for (int i = threadIdx.x; i < 2048; i += 256) {
        int r = i >> 8, f = (i & 255) * 2;
        float a = sx[f * 8 + r], b = sx[f * 8 + 8 + r];
        size_t o = ((size_t)blockIdx.x * 8 + r) * 512 + f;
        *(__half2*)&bx_hi[o] = __halves2half2(__float2half_rn(a), __float2half_rn(b));
    }
}

// bd[h][m][lr] (hi+lo) -> bdt[h][lr][m] hi with inv_d[m] folded; 64x64 tiles
__global__ void convert_d_kernel() {
    __shared__ float tile[64][65];
    const int h = blockIdx.z, j0 = blockIdx.x * 64, m0 = blockIdx.y * 64;
    const int t = threadIdx.x;
    const __half* SH = bd_hi + (size_t)h * N_E * 512;
    const __half* SL = bd_lo + (size_t)h * N_E * 512;
#pragma unroll
    for (int i = 0; i < 8; i++) {
        int ml = (t >> 5) + i * 8, m = m0 + ml;
        float inv = g_inv[2 * N_E + m];
        __half2 vh = *(const __half2*)&SH[(size_t)m * 512 + j0 + (t & 31) * 2];
        __half2 vl = *(const __half2*)&SL[(size_t)m * 512 + j0 + (t & 31) * 2];
        tile[ml][(t & 31) * 2]     = (__half2float(vh.x) + __half2float(vl.x)) * inv;
        tile[ml][(t & 31) * 2 + 1] = (__half2float(vh.y) + __half2float(vl.y)) * inv;
    }
    __syncthreads();
#pragma unroll
    for (int i = 0; i < 8; i++) {
        int jl = (t >> 5) + i * 8;
        float v0 = tile[(t & 31) * 2][jl], v1 = tile[(t & 31) * 2 + 1][jl];
        size_t o = ((size_t)h * 512 + j0 + jl) * N_E + m0 + (t & 31) * 2;
        *(__half2*)&bdt_hi[o] = __halves2half2(__float2half_rn(v0), __float2half_rn(v1));
    }
}

// ============================================================
extern "C" void kernel_launch(void* const* d_in, const int* in_sizes, int n_in,
                              void* d_out, int out_size)
{
    const float* x  = (const float*)d_in[0];
    const float* Wq = (const float*)d_in[1];
    const float* Wk = (const float*)d_in[2];
    const float* Wd = (const float*)d_in[3];
    float* out = (float*)d_out;

    cudaFuncSetAttribute(proj_gemm,    cudaFuncAttributeMaxDynamicSharedMemorySize, SMEM_DYN);
    cudaFuncSetAttribute(scores_gemm,  cudaFuncAttributeMaxDynamicSharedMemorySize, SMEM_DYN);
    cudaFuncSetAttribute(combine_gemm, cudaFuncAttributeMaxDynamicSharedMemorySize, SMEM_DYN);

    zero_kernel<<<64, 256>>>();
    convert_w_kernel<<<768, 256>>>(Wq, Wk, Wd);
    convert_x_kernel<<<N_E, 256>>>(x);
    proj_gemm<<<dim3(64, 12), 256, SMEM_DYN>>>();
    rsqrt_kernel<<<24, 256>>>();
    convert_d_kernel<<<dim3(8, 32, HEAD), 256>>>();
    scores_gemm<<<dim3(8, 16, HEAD), 256, SMEM_DYN>>>();
    combine_gemm<<<dim3(2, 16, HEAD), 256, SMEM_DYN>>>(out);
}

// round 15
// speedup vs baseline: 2.6755x; 1.0373x over previous
#include <cuda_runtime.h>
#include <cuda_fp16.h>
#include <math.h>
#include <stdint.h>

#define N_E   2048
#define HEAD  8
#define HLR   4096

// ---------------- small fp32 scratch ----------------
__device__ float g_sumsq[3 * N_E];
__device__ float g_inv[3 * N_E];            // rsqrt norms (q,k,d)
__device__ float g_rowsum[HEAD * N_E];      // softmax denominators

// ---------------- fp16 operands (1-pass everywhere) ----------------
__device__ __half bx_hi[(size_t)16384 * 512];        // xr[n*8+r][f]        (B of proj)
__device__ __half bw_hi[(size_t)1536 * 512];         // W concat [hq'][f]   (A of proj)
__device__ __half bq_hi[(size_t)HEAD * N_E * 512];   // q [h][n][lr]        (A of scores)
__device__ __half bk_hi[(size_t)HEAD * N_E * 512];   // k                   (B of scores)
__device__ __half bd_hi[(size_t)HEAD * N_E * 512];   // d pre-transpose
__device__ __half bs_hi[(size_t)HEAD * N_E * N_E];   // exp-weights [h][n][m] (A of combine)
__device__ __half bdt_hi[(size_t)HEAD * 512 * N_E];  // dT [h][lr][m], inv_d folded (B of combine)

// ---------------- warp-MMA GEMM core: 128x256x128, 8 warps (2x4), warp tile 64x64 ----------------
#define BM 128
#define BN 256
#define BK 128
#define SA_BYTES (BM * 256)                    // 32768  (256B rows: BK*2)
#define SB_BYTES (BN * 256)                    // 65536
#define STAGE_BYTES (SA_BYTES + SB_BYTES)      // 98304
#define SMEM_DYN (2 * STAGE_BYTES)             // 196608

__device__ __forceinline__ void cp16(uint32_t s, const void* g) {
    asm volatile("cp.async.cg.shared.global [%0], [%1], 16;\n"
                 :: "r"(s), "l"(__cvta_generic_to_global(g)));
}
__device__ __forceinline__ void cp_commit() { asm volatile("cp.async.commit_group;\n" ::: "memory"); }
__device__ __forceinline__ void cp_wait0()  { asm volatile("cp.async.wait_group 0;\n" ::: "memory"); }

__device__ __forceinline__ void ldsm4(uint32_t* r, uint32_t a) {
    asm volatile("ldmatrix.sync.aligned.m8n8.x4.shared.b16 {%0,%1,%2,%3}, [%4];"
                 : "=r"(r[0]), "=r"(r[1]), "=r"(r[2]), "=r"(r[3]) : "r"(a));
}
__device__ __forceinline__ void mma16816(float* c, const uint32_t* a, const uint32_t* b) {
    asm volatile("mma.sync.aligned.m16n8k16.row.col.f32.f16.f16.f32 "
                 "{%0,%1,%2,%3}, {%4,%5,%6,%7}, {%8,%9}, {%0,%1,%2,%3};"
                 : "+f"(c[0]), "+f"(c[1]), "+f"(c[2]), "+f"(c[3])
                 : "r"(a[0]), "r"(a[1]), "r"(a[2]), "r"(a[3]), "r"(b[0]), "r"(b[1]));
}

// one stage: A 128x128 fp16 (32KB), B 256x128 fp16 (64KB); 256B rows, XOR swizzle
__device__ __forceinline__ void load_stage(uint32_t s,
                                           const __half* __restrict__ A,
                                           const __half* __restrict__ B, int ldk) {
    const int tid = threadIdx.x;
#pragma unroll
    for (int i = 0; i < 8; i++) {                       // A: 2048 16B units
        int idx = tid + i * 256, r = idx >> 4, c = idx & 15;
        cp16(s + r * 256 + ((c ^ (r & 7)) << 4), A + (size_t)r * ldk + c * 8);
    }
#pragma unroll
    for (int i = 0; i < 16; i++) {                      // B: 4096 16B units
        int idx = tid + i * 256, r = idx >> 4, c = idx & 15;
        cp16(s + SA_BYTES + r * 256 + ((c ^ (r & 7)) << 4), B + (size_t)r * ldk + c * 8);
    }
    cp_commit();
}

// 1-pass fp16 mainloop over KT k-tiles of 128, 2-stage, ONE barrier per tile
__device__ __forceinline__ void gemm_run(float (&acc)[4][8][4],
    const __half* __restrict__ A, const __half* __restrict__ B,
    const int ldk, const int KT)
{
    extern __shared__ char smem[];
    const uint32_t sb = (uint32_t)__cvta_generic_to_shared(smem);
    const int tid = threadIdx.x, lid = tid & 31, wid = tid >> 5;
    const int mw = wid >> 2, nw = wid & 3;

#pragma unroll
    for (int mf = 0; mf < 4; mf++)
#pragma unroll
        for (int j = 0; j < 8; j++)
#pragma unroll
            for (int e = 0; e < 4; e++) acc[mf][j][e] = 0.f;

    int rowA[4], rowB[4];
#pragma unroll
    for (int mf = 0; mf < 4; mf++)
        rowA[mf] = mw * 64 + mf * 16 + ((lid >> 3) & 1) * 8 + (lid & 7);
#pragma unroll
    for (int nf = 0; nf < 4; nf++)
        rowB[nf] = nw * 64 + nf * 16 + (lid >> 4) * 8 + (lid & 7);
    const int uhA = lid >> 4;
    const int uB  = (lid >> 3) & 1;

    load_stage(sb, A, B, ldk);                           // tile 0 -> stage 0

    for (int t = 0; t < KT; t++) {
        cp_wait0();                                      // tile t resident
        __syncthreads();                                 // ...and all warps past compute(t-1)
        if (t + 1 < KT)                                  // overwrites stage of t-1: safe (post-sync)
            load_stage(sb + ((t + 1) & 1) * STAGE_BYTES,
                       A + (size_t)(t + 1) * BK, B + (size_t)(t + 1) * BK, ldk);

        const uint32_t sA = sb + (t & 1) * STAGE_BYTES;
        const uint32_t sB = sA + SA_BYTES;
#pragma unroll
        for (int ks = 0; ks < 8; ks++) {
            uint32_t a[4][4], b[4][4];
#pragma unroll
            for (int mf = 0; mf < 4; mf++)
                ldsm4(a[mf], sA + rowA[mf] * 256 + (((ks * 2 + uhA) ^ (rowA[mf] & 7)) << 4));
#pragma unroll
            for (int nf = 0; nf < 4; nf++)
                ldsm4(b[nf], sB + rowB[nf] * 256 + (((ks * 2 + uB) ^ (rowB[nf] & 7)) << 4));
#pragma unroll
            for (int mf = 0; mf < 4; mf++)
#pragma unroll
                for (int nf = 0; nf < 4; nf++) {
                    mma16816(acc[mf][nf * 2],     a[mf], &b[nf][0]);
                    mma16816(acc[mf][nf * 2 + 1], a[mf], &b[nf][2]);
                }
        }
    }
}

// ============================================================
// GEMM 1: proj  C[hq'(1536)][c(16384)] = Wcat . xr^T
// epilogue: fp16 store to bq/bk/bd + per-n sumsq atomics
// ============================================================
__global__ __launch_bounds__(256) void proj_gemm() {
    const int row0 = blockIdx.y * BM, col0 = blockIdx.x * BN;
    float acc[4][8][4];
    gemm_run(acc, bw_hi + (size_t)row0 * 512, bx_hi + (size_t)col0 * 512, 512, 4);
    const int lid = threadIdx.x & 31, wid = threadIdx.x >> 5;
    const int mw = wid >> 2, nw = wid & 3;
    const int which = row0 >> 9;                         // 0=q,1=k,2=d
    __half* DH = (which == 0) ? bq_hi : (which == 1) ? bk_hi : bd_hi;

    float psum[8];
#pragma unroll
    for (int j = 0; j < 8; j++) psum[j] = 0.f;

#pragma unroll
    for (int mf = 0; mf < 4; mf++) {
        int row = row0 + mw * 64 + mf * 16 + (lid >> 2);
        int hq = row & 511, h = hq >> 6, ql = hq & 63;
#pragma unroll
        for (int j = 0; j < 8; j++) {
            int col = col0 + nw * 64 + j * 8 + ((lid & 3) << 1);
            int n = col >> 3, r = col & 7;
            float v0 = acc[mf][j][0], v1 = acc[mf][j][1];
            float v2 = acc[mf][j][2], v3 = acc[mf][j][3];
            psum[j] += v0 * v0 + v1 * v1 + v2 * v2 + v3 * v3;
            size_t o0 = ((size_t)(h * N_E + n)) * 512 + ql * 8 + r;
            *(__half2*)&DH[o0]      = __halves2half2(__float2half_rn(v0), __float2half_rn(v1));
            *(__half2*)&DH[o0 + 64] = __halves2half2(__float2half_rn(v2), __float2half_rn(v3));
        }
    }
#pragma unroll
    for (int j = 0; j < 8; j++) {
#pragma unroll
        for (int o = 16; o; o >>= 1) psum[j] += __shfl_xor_sync(0xffffffffu, psum[j], o);
    }
    if (lid == 0) {
        int nb = (col0 >> 3) + nw * 8;
#pragma unroll
        for (int j = 0; j < 8; j++)
            atomicAdd(&g_sumsq[which * N_E + nb + j], psum[j]);
    }
}

// ============================================================
// GEMM 2: scores -> exp-weights.  logit = (q.k)*inv_q[n]*inv_k[m], |logit|<=1
// epilogue: w = exp(logit) -> fp16 + row-sum atomics
// ============================================================
__global__ __launch_bounds__(256) void scores_gemm() {
    const int h = blockIdx.z, row0 = blockIdx.y * BM, col0 = blockIdx.x * BN;
    const size_t ho = (size_t)h * N_E * 512;
    float acc[4][8][4];
    gemm_run(acc, bq_hi + ho + (size_t)row0 * 512, bk_hi + ho + (size_t)col0 * 512, 512, 4);
    const int lid = threadIdx.x & 31, wid = threadIdx.x >> 5;
    const int mw = wid >> 2, nw = wid & 3;
    __half* SH = bs_hi + (size_t)h * N_E * N_E;

    float prow[4][2];
#pragma unroll
    for (int mf = 0; mf < 4; mf++) { prow[mf][0] = 0.f; prow[mf][1] = 0.f; }

#pragma unroll
    for (int mf = 0; mf < 4; mf++) {
        int rA = row0 + mw * 64 + mf * 16 + (lid >> 2);
        float iq0 = g_inv[rA], iq1 = g_inv[rA + 8];
#pragma unroll
        for (int j = 0; j < 8; j++) {
            int col = col0 + nw * 64 + j * 8 + ((lid & 3) << 1);
            float ik0 = g_inv[N_E + col], ik1 = g_inv[N_E + col + 1];
            float e0 = __expf(acc[mf][j][0] * iq0 * ik0);
            float e1 = __expf(acc[mf][j][1] * iq0 * ik1);
            float e2 = __expf(acc[mf][j][2] * iq1 * ik0);
            float e3 = __expf(acc[mf][j][3] * iq1 * ik1);
            prow[mf][0] += e0 + e1;
            prow[mf][1] += e2 + e3;
            size_t o0 = (size_t)rA * N_E + col;
            *(__half2*)&SH[o0]           = __halves2half2(__float2half_rn(e0), __float2half_rn(e1));
            *(__half2*)&SH[o0 + 8 * N_E] = __halves2half2(__float2half_rn(e2), __float2half_rn(e3));
        }
    }
#pragma unroll
    for (int mf = 0; mf < 4; mf++) {
#pragma unroll
        for (int rh = 0; rh < 2; rh++) {
            float v = prow[mf][rh];
            v += __shfl_xor_sync(0xffffffffu, v, 1);
            v += __shfl_xor_sync(0xffffffffu, v, 2);
            if ((lid & 3) == 0) {
                int rA = row0 + mw * 64 + mf * 16 + (lid >> 2) + rh * 8;
                atomicAdd(&g_rowsum[h * N_E + rA], v);
            }
        }
    }
}

// ============================================================
// GEMM 3: combine  out[n][h*512+lr] = (1/rowsum[n]) * sum_m w[n][m] * dT[lr][m]
// ============================================================
__global__ __launch_bounds__(256) void combine_gemm(float* __restrict__ out) {
    const int h = blockIdx.z, row0 = blockIdx.y * BM, col0 = blockIdx.x * BN;
    float acc[4][8][4];
    gemm_run(acc, bs_hi  + (size_t)h * N_E * N_E + (size_t)row0 * N_E,
                  bdt_hi + (size_t)h * 512 * N_E + (size_t)col0 * N_E, N_E, 16);
    const int lid = threadIdx.x & 31, wid = threadIdx.x >> 5;
    const int mw = wid >> 2, nw = wid & 3;
#pragma unroll
    for (int mf = 0; mf < 4; mf++) {
        int row = row0 + mw * 64 + mf * 16 + (lid >> 2);
        float is0 = 1.f / g_rowsum[h * N_E + row];
        float is1 = 1.f / g_rowsum[h * N_E + row + 8];
#pragma unroll
        for (int j = 0; j < 8; j++) {
            int col = col0 + nw * 64 + j * 8 + ((lid & 3) << 1);
            *(float2*)&out[(size_t)row * HLR + h * 512 + col] =
                make_float2(acc[mf][j][0] * is0, acc[mf][j][1] * is0);
            *(float2*)&out[(size_t)(row + 8) * HLR + h * 512 + col] =
                make_float2(acc[mf][j][2] * is1, acc[mf][j][3] * is1);
        }
    }
}

// ============================================================
// converts / small kernels
// ============================================================
__global__ void zero_kernel() {
    int i = blockIdx.x * 256 + threadIdx.x;
    if (i < 3 * N_E) g_sumsq[i] = 0.f;
    if (i < HEAD * N_E) g_rowsum[i] = 0.f;
}

__global__ void rsqrt_kernel() {
    int i = blockIdx.x * 256 + threadIdx.x;
    if (i < 3 * N_E) g_inv[i] = rsqrtf(g_sumsq[i]);
}

__global__ void convert_w_kernel(const float* __restrict__ Wq, const float* __restrict__ Wk,
                                 const float* __restrict__ Wd) {
    int idx = (blockIdx.x * 256 + threadIdx.x) * 4;      // 1536*512 total
    int row = idx >> 9, col = idx & 511;
    const float* src = row < 512 ? Wq : row < 1024 ? Wk : Wd;
    float4 v = *(const float4*)&src[(size_t)(row & 511) * 512 + col];
    __half2* dh = (__half2*)&bw_hi[idx];
    dh[0] = __halves2half2(__float2half_rn(v.x), __float2half_rn(v.y));
    dh[1] = __halves2half2(__float2half_rn(v.z), __float2half_rn(v.w));
}

// x[n][f][r] -> xr[n*8+r][f]
__global__ void convert_x_kernel(const float* __restrict__ x) {
    __shared__ float sx[4096];
    const float* xp = x + (size_t)blockIdx.x * 4096;
    for (int i = threadIdx.x; i < 1024; i += 256)
        ((float4*)sx)[i] = ((const float4*)xp)[i];
    __syncthreads();
    for (int i = threadIdx.x; i < 2048; i += 256) {
        int r = i >> 8, f = (i & 255) * 2;
        float a = sx[f * 8 + r], b = sx[f * 8 + 8 + r];
        size_t o = ((size_t)blockIdx.x * 8 + r) * 512 + f;
        *(__half2*)&bx_hi[o] = __halves2half2(__float2half_rn(a), __float2half_rn(b));
    }
}

// bd[h][m][lr] -> bdt[h][lr][m] with inv_d[m] folded; 64x64 tiles
__global__ void convert_d_kernel() {
    __shared__ float tile[64][65];
    const int h = blockIdx.z, j0 = blockIdx.x * 64, m0 = blockIdx.y * 64;
    const int t = threadIdx.x;
    const __half* SH = bd_hi + (size_t)h * N_E * 512;
#pragma unroll
    for (int i = 0; i < 8; i++) {
        int ml = (t >> 5) + i * 8, m = m0 + ml;
        float inv = g_inv[2 * N_E + m];
        __half2 vh = *(const __half2*)&SH[(size_t)m * 512 + j0 + (t & 31) * 2];
        tile[ml][(t & 31) * 2]     = __half2float(vh.x) * inv;
        tile[ml][(t & 31) * 2 + 1] = __half2float(vh.y) * inv;
    }
    __syncthreads();
#pragma unroll
    for (int i = 0; i < 8; i++) {
        int jl = (t >> 5) + i * 8;
        float v0 = tile[(t & 31) * 2][jl], v1 = tile[(t & 31) * 2 + 1][jl];
        size_t o = ((size_t)h * 512 + j0 + jl) * N_E + m0 + (t & 31) * 2;
        *(__half2*)&bdt_hi[o] = __halves2half2(__float2half_rn(v0), __float2half_rn(v1));
    }
}

// ============================================================
extern "C" void kernel_launch(void* const* d_in, const int* in_sizes, int n_in,
                              void* d_out, int out_size)
{
    const float* x  = (const float*)d_in[0];
    const float* Wq = (const float*)d_in[1];
    const float* Wk = (const float*)d_in[2];
    const float* Wd = (const float*)d_in[3];
    float* out = (float*)d_out;

    cudaFuncSetAttribute(proj_gemm,    cudaFuncAttributeMaxDynamicSharedMemorySize, SMEM_DYN);
    cudaFuncSetAttribute(scores_gemm,  cudaFuncAttributeMaxDynamicSharedMemorySize, SMEM_DYN);
    cudaFuncSetAttribute(combine_gemm, cudaFuncAttributeMaxDynamicSharedMemorySize, SMEM_DYN);

    zero_kernel<<<64, 256>>>();
    convert_w_kernel<<<768, 256>>>(Wq, Wk, Wd);
    convert_x_kernel<<<N_E, 256>>>(x);
    proj_gemm<<<dim3(64, 12), 256, SMEM_DYN>>>();
    rsqrt_kernel<<<24, 256>>>();
    convert_d_kernel<<<dim3(8, 32, HEAD), 256>>>();
    scores_gemm<<<dim3(8, 16, HEAD), 256, SMEM_DYN>>>();
    combine_gemm<<<dim3(2, 16, HEAD), 256, SMEM_DYN>>>(out);
}

// round 16
// speedup vs baseline: 2.8749x; 1.0745x over previous
#include <cuda_runtime.h>
#include <cuda_fp16.h>
#include <math.h>
#include <stdint.h>

#define N_E   2048
#define HEAD  8
#define HLR   4096

// ---------------- small fp32 scratch ----------------
__device__ float g_sumsq[3 * N_E];
__device__ float g_inv[3 * N_E];            // rsqrt norms (q,k,d)
__device__ float g_rowsum[HEAD * N_E];      // softmax denominators

// ---------------- fp16 operands (1-pass everywhere) ----------------
__device__ __half bx_hi[(size_t)16384 * 512];        // xr[n*8+r][f]        (B of proj)
__device__ __half bw_hi[(size_t)1536 * 512];         // W concat [hq'][f]   (A of proj)
__device__ __half bq_hi[(size_t)HEAD * N_E * 512];   // q [h][n][lr]        (A of scores)
__device__ __half bk_hi[(size_t)HEAD * N_E * 512];   // k                   (B of scores)
__device__ __half bd_hi[(size_t)HEAD * N_E * 512];   // d pre-transpose
__device__ __half bs_hi[(size_t)HEAD * N_E * N_E];   // exp-weights [h][n][m] (A of combine)
__device__ __half bdt_hi[(size_t)HEAD * 512 * N_E];  // dT [h][lr][m], inv_d folded (B of combine)

// ---- warp-MMA GEMM core: 128x128x64 CTA tile, 4 warps (2x2), warp tile 64x64, 2 CTAs/SM ----
#define BM 128
#define BN 128
#define BK 64
#define STG 3
#define SA_BYTES (BM * 128)                    // 16384 (128B rows)
#define SB_BYTES (BN * 128)                    // 16384
#define STAGE_BYTES (SA_BYTES + SB_BYTES)      // 32768
#define SMEM_DYN (STG * STAGE_BYTES)           // 98304 -> 2 CTAs/SM (192KB)
#define NTHREADS 128

__device__ __forceinline__ void cp16(uint32_t s, const void* g) {
    asm volatile("cp.async.cg.shared.global [%0], [%1], 16;\n"
                 :: "r"(s), "l"(__cvta_generic_to_global(g)));
}
__device__ __forceinline__ void cp_commit() { asm volatile("cp.async.commit_group;\n" ::: "memory"); }
__device__ __forceinline__ void cp_wait1()  { asm volatile("cp.async.wait_group 1;\n" ::: "memory"); }

__device__ __forceinline__ void ldsm4(uint32_t* r, uint32_t a) {
    asm volatile("ldmatrix.sync.aligned.m8n8.x4.shared.b16 {%0,%1,%2,%3}, [%4];"
                 : "=r"(r[0]), "=r"(r[1]), "=r"(r[2]), "=r"(r[3]) : "r"(a));
}
__device__ __forceinline__ void mma16816(float* c, const uint32_t* a, const uint32_t* b) {
    asm volatile("mma.sync.aligned.m16n8k16.row.col.f32.f16.f16.f32 "
                 "{%0,%1,%2,%3}, {%4,%5,%6,%7}, {%8,%9}, {%0,%1,%2,%3};"
                 : "+f"(c[0]), "+f"(c[1]), "+f"(c[2]), "+f"(c[3])
                 : "r"(a[0]), "r"(a[1]), "r"(a[2]), "r"(a[3]), "r"(b[0]), "r"(b[1]));
}

// one stage: A 128x64 fp16 (16KB) + B 128x64 fp16 (16KB); 128B rows, unit-XOR swizzle
__device__ __forceinline__ void load_stage(uint32_t s,
                                           const __half* __restrict__ A,
                                           const __half* __restrict__ B, int ldk) {
    const int tid = threadIdx.x;
#pragma unroll
    for (int i = 0; i < 8; i++) {                       // A: 1024 16B units
        int idx = tid + i * NTHREADS, r = idx >> 3, c = idx & 7;
        cp16(s + r * 128 + ((c ^ (r & 7)) << 4), A + (size_t)r * ldk + c * 8);
    }
#pragma unroll
    for (int i = 0; i < 8; i++) {                       // B: 1024 16B units
        int idx = tid + i * NTHREADS, r = idx >> 3, c = idx & 7;
        cp16(s + SA_BYTES + r * 128 + ((c ^ (r & 7)) << 4), B + (size_t)r * ldk + c * 8);
    }
    cp_commit();
}

// 1-pass fp16 mainloop, 3 stages, one barrier per tile (R13 schedule)
__device__ __forceinline__ void gemm_run(float (&acc)[4][8][4],
    const __half* __restrict__ A, const __half* __restrict__ B,
    const int ldk, const int KT)
{
    extern __shared__ char smem[];
    const uint32_t sb = (uint32_t)__cvta_generic_to_shared(smem);
    const int lid = threadIdx.x & 31, wid = threadIdx.x >> 5;
    const int mw = wid >> 1, nw = wid & 1;

#pragma unroll
    for (int mf = 0; mf < 4; mf++)
#pragma unroll
        for (int j = 0; j < 8; j++)
#pragma unroll
            for (int e = 0; e < 4; e++) acc[mf][j][e] = 0.f;

    int rowA[4], rowB[4];
#pragma unroll
    for (int mf = 0; mf < 4; mf++)
        rowA[mf] = mw * 64 + mf * 16 + ((lid >> 3) & 1) * 8 + (lid & 7);
#pragma unroll
    for (int nf = 0; nf < 4; nf++)
        rowB[nf] = nw * 64 + nf * 16 + (lid >> 4) * 8 + (lid & 7);
    const int uhA = lid >> 4;
    const int uB  = (lid >> 3) & 1;

    load_stage(sb, A, B, ldk);                                       // tile 0 -> stage 0
    load_stage(sb + STAGE_BYTES, A + BK, B + BK, ldk);               // tile 1 -> stage 1

    for (int t = 0; t < KT; t++) {
        cp_wait1();                                      // tile t resident (t+1 may be in flight)
        __syncthreads();                                 // all warps past compute(t-1)
        if (t + 2 < KT)                                  // stage (t+2)%3 = stage(t-1): safe post-sync
            load_stage(sb + ((t + 2) % STG) * STAGE_BYTES,
                       A + (size_t)(t + 2) * BK, B + (size_t)(t + 2) * BK, ldk);
        else
            cp_commit();                                 // keep group accounting uniform

        const uint32_t sA = sb + (t % STG) * STAGE_BYTES;
        const uint32_t sB = sA + SA_BYTES;
#pragma unroll
        for (int ks = 0; ks < 4; ks++) {
            uint32_t a[4][4], b[4][4];
#pragma unroll
            for (int mf = 0; mf < 4; mf++)
                ldsm4(a[mf], sA + rowA[mf] * 128 + (((ks * 2 + uhA) ^ (rowA[mf] & 7)) << 4));
#pragma unroll
            for (int nf = 0; nf < 4; nf++)
                ldsm4(b[nf], sB + rowB[nf] * 128 + (((ks * 2 + uB) ^ (rowB[nf] & 7)) << 4));
#pragma unroll
            for (int mf = 0; mf < 4; mf++)
#pragma unroll
                for (int nf = 0; nf < 4; nf++) {
                    mma16816(acc[mf][nf * 2],     a[mf], &b[nf][0]);
                    mma16816(acc[mf][nf * 2 + 1], a[mf], &b[nf][2]);
                }
        }
    }
}

// ============================================================
// GEMM 1: proj  C[hq'(1536)][c(16384)] = Wcat . xr^T
// ============================================================
__global__ __launch_bounds__(NTHREADS) void proj_gemm() {
    const int row0 = blockIdx.y * BM, col0 = blockIdx.x * BN;
    float acc[4][8][4];
    gemm_run(acc, bw_hi + (size_t)row0 * 512, bx_hi + (size_t)col0 * 512, 512, 8);
    const int lid = threadIdx.x & 31, wid = threadIdx.x >> 5;
    const int mw = wid >> 1, nw = wid & 1;
    const int which = row0 >> 9;                         // 0=q,1=k,2=d
    __half* DH = (which == 0) ? bq_hi : (which == 1) ? bk_hi : bd_hi;

    float psum[8];
#pragma unroll
    for (int j = 0; j < 8; j++) psum[j] = 0.f;

#pragma unroll
    for (int mf = 0; mf < 4; mf++) {
        int row = row0 + mw * 64 + mf * 16 + (lid >> 2);
        int hq = row & 511, h = hq >> 6, ql = hq & 63;
#pragma unroll
        for (int j = 0; j < 8; j++) {
            int col = col0 + nw * 64 + j * 8 + ((lid & 3) << 1);
            int n = col >> 3, r = col & 7;
            float v0 = acc[mf][j][0], v1 = acc[mf][j][1];
            float v2 = acc[mf][j][2], v3 = acc[mf][j][3];
            psum[j] += v0 * v0 + v1 * v1 + v2 * v2 + v3 * v3;
            size_t o0 = ((size_t)(h * N_E + n)) * 512 + ql * 8 + r;
            *(__half2*)&DH[o0]      = __halves2half2(__float2half_rn(v0), __float2half_rn(v1));
            *(__half2*)&DH[o0 + 64] = __halves2half2(__float2half_rn(v2), __float2half_rn(v3));
        }
    }
#pragma unroll
    for (int j = 0; j < 8; j++) {
#pragma unroll
        for (int o = 16; o; o >>= 1) psum[j] += __shfl_xor_sync(0xffffffffu, psum[j], o);
    }
    if (lid == 0) {
        int nb = (col0 >> 3) + nw * 8;
#pragma unroll
        for (int j = 0; j < 8; j++)
            atomicAdd(&g_sumsq[which * N_E + nb + j], psum[j]);
    }
}

// ============================================================
// GEMM 2: scores -> exp-weights.  logit = (q.k)*inv_q[n]*inv_k[m], |logit|<=1
// ============================================================
__global__ __launch_bounds__(NTHREADS) void scores_gemm() {
    const int h = blockIdx.z, row0 = blockIdx.y * BM, col0 = blockIdx.x * BN;
    const size_t ho = (size_t)h * N_E * 512;
    float acc[4][8][4];
    gemm_run(acc, bq_hi + ho + (size_t)row0 * 512, bk_hi + ho + (size_t)col0 * 512, 512, 8);
    const int lid = threadIdx.x & 31, wid = threadIdx.x >> 5;
    const int mw = wid >> 1, nw = wid & 1;
    __half* SH = bs_hi + (size_t)h * N_E * N_E;

    float prow[4][2];
#pragma unroll
    for (int mf = 0; mf < 4; mf++) { prow[mf][0] = 0.f; prow[mf][1] = 0.f; }

#pragma unroll
    for (int mf = 0; mf < 4; mf++) {
        int rA = row0 + mw * 64 + mf * 16 + (lid >> 2);
        float iq0 = g_inv[rA], iq1 = g_inv[rA + 8];
#pragma unroll
        for (int j = 0; j < 8; j++) {
            int col = col0 + nw * 64 + j * 8 + ((lid & 3) << 1);
            float ik0 = g_inv[N_E + col], ik1 = g_inv[N_E + col + 1];
            float e0 = __expf(acc[mf][j][0] * iq0 * ik0);
            float e1 = __expf(acc[mf][j][1] * iq0 * ik1);
            float e2 = __expf(acc[mf][j][2] * iq1 * ik0);
            float e3 = __expf(acc[mf][j][3] * iq1 * ik1);
            prow[mf][0] += e0 + e1;
            prow[mf][1] += e2 + e3;
            size_t o0 = (size_t)rA * N_E + col;
            *(__half2*)&SH[o0]           = __halves2half2(__float2half_rn(e0), __float2half_rn(e1));
            *(__half2*)&SH[o0 + 8 * N_E] = __halves2half2(__float2half_rn(e2), __float2half_rn(e3));
        }
    }
#pragma unroll
    for (int mf = 0; mf < 4; mf++) {
#pragma unroll
        for (int rh = 0; rh < 2; rh++) {
            float v = prow[mf][rh];
            v += __shfl_xor_sync(0xffffffffu, v, 1);
            v += __shfl_xor_sync(0xffffffffu, v, 2);
            if ((lid & 3) == 0) {
                int rA = row0 + mw * 64 + mf * 16 + (lid >> 2) + rh * 8;
                atomicAdd(&g_rowsum[h * N_E + rA], v);
            }
        }
    }
}

// ============================================================
// GEMM 3: combine  out[n][h*512+lr] = (1/rowsum[n]) * sum_m w[n][m] * dT[lr][m]
// ============================================================
__global__ __launch_bounds__(NTHREADS) void combine_gemm(float* __restrict__ out) {
    const int h = blockIdx.z, row0 = blockIdx.y * BM, col0 = blockIdx.x * BN;
    float acc[4][8][4];
    gemm_run(acc, bs_hi  + (size_t)h * N_E * N_E + (size_t)row0 * N_E,
                  bdt_hi + (size_t)h * 512 * N_E + (size_t)col0 * N_E, N_E, 32);
    const int lid = threadIdx.x & 31, wid = threadIdx.x >> 5;
    const int mw = wid >> 1, nw = wid & 1;
#pragma unroll
    for (int mf = 0; mf < 4; mf++) {
        int row = row0 + mw * 64 + mf * 16 + (lid >> 2);
        float is0 = 1.f / g_rowsum[h * N_E + row];
        float is1 = 1.f / g_rowsum[h * N_E + row + 8];
#pragma unroll
        for (int j = 0; j < 8; j++) {
            int col = col0 + nw * 64 + j * 8 + ((lid & 3) << 1);
            *(float2*)&out[(size_t)row * HLR + h * 512 + col] =
                make_float2(acc[mf][j][0] * is0, acc[mf][j][1] * is0);
            *(float2*)&out[(size_t)(row + 8) * HLR + h * 512 + col] =
                make_float2(acc[mf][j][2] * is1, acc[mf][j][3] * is1);
        }
    }
}

// ============================================================
// converts / small kernels
// ============================================================
__global__ void zero_kernel() {
    int i = blockIdx.x * 256 + threadIdx.x;
    if (i < 3 * N_E) g_sumsq[i] = 0.f;
    if (i < HEAD * N_E) g_rowsum[i] = 0.f;
}

__global__ void rsqrt_kernel() {
    int i = blockIdx.x * 256 + threadIdx.x;
    if (i < 3 * N_E) g_inv[i] = rsqrtf(g_sumsq[i]);
}

__global__ void convert_w_kernel(const float* __restrict__ Wq, const float* __restrict__ Wk,
                                 const float* __restrict__ Wd) {
    int idx = (blockIdx.x * 256 + threadIdx.x) * 4;      // 1536*512 total
    int row = idx >> 9, col = idx & 511;
    const float* src = row < 512 ? Wq : row < 1024 ? Wk : Wd;
    float4 v = *(const float4*)&src[(size_t)(row & 511) * 512 + col];
    __half2* dh = (__half2*)&bw_hi[idx];
    dh[0] = __halves2half2(__float2half_rn(v.x), __float2half_rn(v.y));
    dh[1] = __halves2half2(__float2half_rn(v.z), __float2half_rn(v.w));
}

// x[n][f][r] -> xr[n*8+r][f]
__global__ void convert_x_kernel(const float* __restrict__ x) {
    __shared__ float sx[4096];
    const float* xp = x + (size_t)blockIdx.x * 4096;
    for (int i = threadIdx.x; i < 1024; i += 256)
        ((float4*)sx)[i] = ((const float4*)xp)[i];
    __syncthreads();
    for (int i = threadIdx.x; i < 2048; i += 256) {
        int r = i >> 8, f = (i & 255) * 2;
        float a = sx[f * 8 + r], b = sx[f * 8 + 8 + r];
        size_t o = ((size_t)blockIdx.x * 8 + r) * 512 + f;
        *(__half2*)&bx_hi[o] = __halves2half2(__float2half_rn(a), __float2half_rn(b));
    }
}

// bd[h][m][lr] -> bdt[h][lr][m] with inv_d[m] folded; 64x64 tiles
__global__ void convert_d_kernel() {
    __shared__ float tile[64][65];
    const int h = blockIdx.z, j0 = blockIdx.x * 64, m0 = blockIdx.y * 64;
    const int t = threadIdx.x;
    const __half* SH = bd_hi + (size_t)h * N_E * 512;
#pragma unroll
    for (int i = 0; i < 8; i++) {
        int ml = (t >> 5) + i * 8, m = m0 + ml;
        float inv = g_inv[2 * N_E + m];
        __half2 vh = *(const __half2*)&SH[(size_t)m * 512 + j0 + (t & 31) * 2];
        tile[ml][(t & 31) * 2]     = __half2float(vh.x) * inv;
        tile[ml][(t & 31) * 2 + 1] = __half2float(vh.y) * inv;
    }
    __syncthreads();
#pragma unroll
    for (int i = 0; i < 8; i++) {
        int jl = (t >> 5) + i * 8;
        float v0 = tile[(t & 31) * 2][jl], v1 = tile[(t & 31) * 2 + 1][jl];
        size_t o = ((size_t)h * 512 + j0 + jl) * N_E + m0 + (t & 31) * 2;
        *(__half2*)&bdt_hi[o] = __halves2half2(__float2half_rn(v0), __float2half_rn(v1));
    }
}

// ============================================================
extern "C" void kernel_launch(void* const* d_in, const int* in_sizes, int n_in,
                              void* d_out, int out_size)
{
    const float* x  = (const float*)d_in[0];
    const float* Wq = (const float*)d_in[1];
    const float* Wk = (const float*)d_in[2];
    const float* Wd = (const float*)d_in[3];
    float* out = (float*)d_out;

    cudaFuncSetAttribute(proj_gemm,    cudaFuncAttributeMaxDynamicSharedMemorySize, SMEM_DYN);
    cudaFuncSetAttribute(scores_gemm,  cudaFuncAttributeMaxDynamicSharedMemorySize, SMEM_DYN);
    cudaFuncSetAttribute(combine_gemm, cudaFuncAttributeMaxDynamicSharedMemorySize, SMEM_DYN);

    zero_kernel<<<64, 256>>>();
    convert_w_kernel<<<768, 256>>>(Wq, Wk, Wd);
    convert_x_kernel<<<N_E, 256>>>(x);
    proj_gemm<<<dim3(128, 12), NTHREADS, SMEM_DYN>>>();
    rsqrt_kernel<<<24, 256>>>();
    convert_d_kernel<<<dim3(8, 32, HEAD), 256>>>();
    scores_gemm<<<dim3(16, 16, HEAD), NTHREADS, SMEM_DYN>>>();
    combine_gemm<<<dim3(4, 16, HEAD), NTHREADS, SMEM_DYN>>>(out);
}